// round 5
// baseline (speedup 1.0000x reference)
#include <cuda_runtime.h>

// ShiftDecoderNet fused kernel: 3-layer MLP (LN+ReLU) + softmax + causal shift-sum.
// One CTA = 64 rows. 8 warps x 8 rows/warp. Each lane owns 8 output cols
// (j = 4*lane .. 4*lane+3 and 128+4*lane .. +3) x 8 rows of fp32 accumulators,
// packed as f32x2 for fma.rn.f32x2. Weights staged through a 128KB shared buffer.

#define BITS 64
#define HID 256
#define RB 64      // rows per block
#define NT 256     // threads per block
#define RW 8       // rows per warp

__device__ __forceinline__ void ffma2(unsigned long long &c, unsigned long long a, unsigned long long b) {
    asm("fma.rn.f32x2 %0, %1, %2, %0;" : "+l"(c) : "l"(a), "l"(b));
}
__device__ __forceinline__ unsigned long long dup2(float x) {
    unsigned long long d;
    asm("mov.b64 %0, {%1, %1};" : "=l"(d) : "f"(x));
    return d;
}
__device__ __forceinline__ float2 unpk(unsigned long long v) {
    float2 r;
    asm("mov.b64 {%0, %1}, %2;" : "=f"(r.x), "=f"(r.y) : "l"(v));
    return r;
}
__device__ __forceinline__ float wredsum(float v) {
    #pragma unroll
    for (int o = 16; o; o >>= 1) v += __shfl_xor_sync(0xffffffffu, v, o);
    return v;
}
__device__ __forceinline__ float wredmax(float v) {
    #pragma unroll
    for (int o = 16; o; o >>= 1) v = fmaxf(v, __shfl_xor_sync(0xffffffffu, v, o));
    return v;
}

// Shared layout (floats):
//   sBUF: [0, 32768)          128KB weight staging (W1T / W2 half / W3T)
//   sH:   [32768, 49152)      64 rows x 256 activations (h1, then h2, then probs)
//   sX:   [49152, 53248)      64 x 64 shift_bits
//   sA:   [53248, 57344)      64 x 64 a_bits
#define SMEM_FLOATS 57344

extern "C" __global__ void __launch_bounds__(NT, 1)
shiftdec_fused(const float* __restrict__ a_bits, const float* __restrict__ shift_bits,
               const float* __restrict__ W1, const float* __restrict__ b1,
               const float* __restrict__ g1, const float* __restrict__ be1,
               const float* __restrict__ W2, const float* __restrict__ b2,
               const float* __restrict__ g2, const float* __restrict__ be2,
               const float* __restrict__ W3, const float* __restrict__ b3,
               float* __restrict__ out)
{
    extern __shared__ float smem[];
    float* sBUF = smem;
    float* sH   = smem + 32768;
    float* sX   = smem + 49152;
    float* sA   = smem + 53248;

    const int tid = threadIdx.x;
    const int l   = tid & 31;
    const int w   = tid >> 5;
    const int wr  = w * RW;                 // local row base for this warp
    const int r0  = blockIdx.x * RB;        // global row base
    const int j0  = l * 4;

    // ---- cooperative loads: sX, sA (vectorized), W1T into sBUF ----
    {
        const float4* xs = (const float4*)(shift_bits + (size_t)r0 * BITS);
        const float4* as = (const float4*)(a_bits + (size_t)r0 * BITS);
        float4* dx = (float4*)sX;
        float4* da = (float4*)sA;
        #pragma unroll
        for (int it = 0; it < (RB * BITS / 4) / NT; ++it) {
            dx[tid + NT * it] = xs[tid + NT * it];
            da[tid + NT * it] = as[tid + NT * it];
        }
        // W1T: sBUF[k*256 + j] = W1[j*64 + k]; thread tid streams row j=tid.
        #pragma unroll
        for (int it = 0; it < 16; ++it) {
            float4 v = *(const float4*)(W1 + tid * 64 + 4 * it);
            sBUF[(4 * it + 0) * 256 + tid] = v.x;
            sBUF[(4 * it + 1) * 256 + tid] = v.y;
            sBUF[(4 * it + 2) * 256 + tid] = v.z;
            sBUF[(4 * it + 3) * 256 + tid] = v.w;
        }
    }
    __syncthreads();

    // ================= Stage 1: h1 = relu(LN(x @ W1^T + b1)) =================
    unsigned long long acc[RW][4];
    #pragma unroll
    for (int r = 0; r < RW; ++r)
        #pragma unroll
        for (int p = 0; p < 4; ++p) acc[r][p] = 0ull;

    for (int k = 0; k < 64; ++k) {
        const float* wrow = sBUF + (k << 8);
        ulonglong2 wa = *(const ulonglong2*)(wrow + j0);
        ulonglong2 wb = *(const ulonglong2*)(wrow + 128 + j0);
        #pragma unroll
        for (int r = 0; r < RW; ++r) {
            unsigned long long hd = dup2(sX[(wr + r) * 64 + k]);
            ffma2(acc[r][0], wa.x, hd);
            ffma2(acc[r][1], wa.y, hd);
            ffma2(acc[r][2], wb.x, hd);
            ffma2(acc[r][3], wb.y, hd);
        }
    }

    // LN1 + ReLU -> sH (own rows)
    {
        float bj[8], gj[8], bej[8];
        #pragma unroll
        for (int c = 0; c < 4; ++c) {
            bj[c]      = b1[j0 + c];        bj[4 + c]  = b1[128 + j0 + c];
            gj[c]      = g1[j0 + c];        gj[4 + c]  = g1[128 + j0 + c];
            bej[c]     = be1[j0 + c];       bej[4 + c] = be1[128 + j0 + c];
        }
        #pragma unroll
        for (int r = 0; r < RW; ++r) {
            float v[8]; float2 t;
            t = unpk(acc[r][0]); v[0] = t.x + bj[0]; v[1] = t.y + bj[1];
            t = unpk(acc[r][1]); v[2] = t.x + bj[2]; v[3] = t.y + bj[3];
            t = unpk(acc[r][2]); v[4] = t.x + bj[4]; v[5] = t.y + bj[5];
            t = unpk(acc[r][3]); v[6] = t.x + bj[6]; v[7] = t.y + bj[7];
            float s = 0.f, s2 = 0.f;
            #pragma unroll
            for (int c = 0; c < 8; ++c) { s += v[c]; s2 += v[c] * v[c]; }
            s = wredsum(s); s2 = wredsum(s2);
            float mean = s * (1.0f / 256.0f);
            float var  = s2 * (1.0f / 256.0f) - mean * mean;
            float rstd = rsqrtf(var + 1e-5f);
            float h[8];
            #pragma unroll
            for (int c = 0; c < 8; ++c)
                h[c] = fmaxf(0.f, (v[c] - mean) * rstd * gj[c] + bej[c]);
            float* hp = sH + (wr + r) * 256;
            *(float4*)(hp + j0)       = make_float4(h[0], h[1], h[2], h[3]);
            *(float4*)(hp + 128 + j0) = make_float4(h[4], h[5], h[6], h[7]);
        }
    }
    __syncthreads();   // everyone done with sBUF(W1) and writing sH

    // ================= Stage 2: h2 = relu(LN(h1 @ W2^T + b2)) =================
    #pragma unroll
    for (int r = 0; r < RW; ++r)
        #pragma unroll
        for (int p = 0; p < 4; ++p) acc[r][p] = 0ull;

    #pragma unroll 1
    for (int pass = 0; pass < 2; ++pass) {
        const int k0 = pass * 128;
        // load W2 half: sBUF[k*256 + j] = W2[j*256 + k0 + k]; thread streams row j=tid
        #pragma unroll
        for (int it = 0; it < 32; ++it) {
            float4 v = *(const float4*)(W2 + tid * 256 + k0 + 4 * it);
            sBUF[(4 * it + 0) * 256 + tid] = v.x;
            sBUF[(4 * it + 1) * 256 + tid] = v.y;
            sBUF[(4 * it + 2) * 256 + tid] = v.z;
            sBUF[(4 * it + 3) * 256 + tid] = v.w;
        }
        __syncthreads();

        for (int k = 0; k < 128; ++k) {
            const float* wrow = sBUF + (k << 8);
            ulonglong2 wa = *(const ulonglong2*)(wrow + j0);
            ulonglong2 wb = *(const ulonglong2*)(wrow + 128 + j0);
            #pragma unroll
            for (int r = 0; r < RW; ++r) {
                unsigned long long hd = dup2(sH[(wr + r) * 256 + k0 + k]);
                ffma2(acc[r][0], wa.x, hd);
                ffma2(acc[r][1], wa.y, hd);
                ffma2(acc[r][2], wb.x, hd);
                ffma2(acc[r][3], wb.y, hd);
            }
        }
        __syncthreads();   // free sBUF for next fill
    }

    // load W3T while sBUF is free: sBUF[k*64 + j] = W3[j*256 + k]
    {
        const int j  = tid & 63;
        const int ks = (tid >> 6) * 64;    // 64-wide k segment
        #pragma unroll
        for (int it = 0; it < 16; ++it) {
            float4 v = *(const float4*)(W3 + j * 256 + ks + 4 * it);
            sBUF[(ks + 4 * it + 0) * 64 + j] = v.x;
            sBUF[(ks + 4 * it + 1) * 64 + j] = v.y;
            sBUF[(ks + 4 * it + 2) * 64 + j] = v.z;
            sBUF[(ks + 4 * it + 3) * 64 + j] = v.w;
        }
    }

    // LN2 + ReLU -> overwrite sH (own rows only)
    {
        float bj[8], gj[8], bej[8];
        #pragma unroll
        for (int c = 0; c < 4; ++c) {
            bj[c]      = b2[j0 + c];        bj[4 + c]  = b2[128 + j0 + c];
            gj[c]      = g2[j0 + c];        gj[4 + c]  = g2[128 + j0 + c];
            bej[c]     = be2[j0 + c];       bej[4 + c] = be2[128 + j0 + c];
        }
        #pragma unroll
        for (int r = 0; r < RW; ++r) {
            float v[8]; float2 t;
            t = unpk(acc[r][0]); v[0] = t.x + bj[0]; v[1] = t.y + bj[1];
            t = unpk(acc[r][1]); v[2] = t.x + bj[2]; v[3] = t.y + bj[3];
            t = unpk(acc[r][2]); v[4] = t.x + bj[4]; v[5] = t.y + bj[5];
            t = unpk(acc[r][3]); v[6] = t.x + bj[6]; v[7] = t.y + bj[7];
            float s = 0.f, s2 = 0.f;
            #pragma unroll
            for (int c = 0; c < 8; ++c) { s += v[c]; s2 += v[c] * v[c]; }
            s = wredsum(s); s2 = wredsum(s2);
            float mean = s * (1.0f / 256.0f);
            float var  = s2 * (1.0f / 256.0f) - mean * mean;
            float rstd = rsqrtf(var + 1e-5f);
            float h[8];
            #pragma unroll
            for (int c = 0; c < 8; ++c)
                h[c] = fmaxf(0.f, (v[c] - mean) * rstd * gj[c] + bej[c]);
            float* hp = sH + (wr + r) * 256;
            *(float4*)(hp + j0)       = make_float4(h[0], h[1], h[2], h[3]);
            *(float4*)(hp + 128 + j0) = make_float4(h[4], h[5], h[6], h[7]);
        }
    }
    __syncthreads();   // W3T loaded + h2 visible

    // ================= Stage 3: logits = h2 @ W3^T + b3 =================
    unsigned long long a3[RW];
    #pragma unroll
    for (int r = 0; r < RW; ++r) a3[r] = 0ull;

    for (int k = 0; k < 256; ++k) {
        unsigned long long wp = *(const unsigned long long*)(sBUF + (k << 6) + 2 * l);
        #pragma unroll
        for (int r = 0; r < RW; ++r) {
            unsigned long long hd = dup2(sH[(wr + r) * 256 + k]);
            ffma2(a3[r], wp, hd);
        }
    }

    // ================= Softmax + causal shift-sum =================
    const float b3a = b3[2 * l];
    const float b3b = b3[2 * l + 1];
    #pragma unroll
    for (int r = 0; r < RW; ++r) {
        float2 t = unpk(a3[r]);
        float l0 = t.x + b3a, l1 = t.y + b3b;
        float m = wredmax(fmaxf(l0, l1));
        float e0 = expf(l0 - m), e1 = expf(l1 - m);
        float sum = wredsum(e0 + e1);
        float inv = 1.0f / sum;
        // store probs into sH row (h2 region no longer needed)
        *(float2*)(sH + (wr + r) * 256 + 2 * l) = make_float2(e0 * inv, e1 * inv);
    }
    __syncwarp();

    const int i0 = 2 * l, i1 = 2 * l + 1;
    #pragma unroll
    for (int r = 0; r < RW; ++r) {
        const float* pr = sH + (wr + r) * 256;
        const float* ar = sA + (wr + r) * 64;
        float o0 = 0.f, o1 = 0.f;
        for (int s = 0; s <= i1; ++s) {
            float pv = pr[s];
            if (s <= i0) o0 += pv * ar[i0 - s];
            o1 += pv * ar[i1 - s];
        }
        *(float2*)(out + (size_t)(r0 + wr + r) * 64 + i0) = make_float2(o0, o1);
    }
}

extern "C" void kernel_launch(void* const* d_in, const int* in_sizes, int n_in,
                              void* d_out, int out_size)
{
    const float* a_bits     = (const float*)d_in[0];
    const float* shift_bits = (const float*)d_in[1];
    const float* W1  = (const float*)d_in[2];
    const float* b1  = (const float*)d_in[3];
    const float* g1  = (const float*)d_in[4];
    const float* be1 = (const float*)d_in[5];
    const float* W2  = (const float*)d_in[6];
    const float* b2  = (const float*)d_in[7];
    const float* g2  = (const float*)d_in[8];
    const float* be2 = (const float*)d_in[9];
    const float* W3  = (const float*)d_in[10];
    const float* b3  = (const float*)d_in[11];
    float* out = (float*)d_out;

    const int B = in_sizes[0] / BITS;     // 32768
    const int grid = B / RB;              // 512

    static int smem_bytes = SMEM_FLOATS * (int)sizeof(float);   // 229376
    cudaFuncSetAttribute(shiftdec_fused,
                         cudaFuncAttributeMaxDynamicSharedMemorySize, smem_bytes);
    shiftdec_fused<<<grid, NT, smem_bytes>>>(a_bits, shift_bits,
                                             W1, b1, g1, be1,
                                             W2, b2, g2, be2,
                                             W3, b3, out);
}

// round 8
// speedup vs baseline: 2.1315x; 2.1315x over previous
#include <cuda_runtime.h>
#include <cuda_bf16.h>
#include <cstdint>

// ShiftDecoderNet via mma.sync m16n8k16 bf16 (fp32 acc), split-bf16 precision.
// CTA = 128 rows (8 warps x 16-row stripes), grid = 256.

#define NT 256
#define OFF_P   0        // params: 1600 floats
#define OFF_X   7040     // X bf16 [128][144B]
#define OFF_A   25600    // a_bits bf16 [128][144B]
#define OFF_W   44032    // weight chunk hi (<=20.5KB)
#define OFF_WLO 64512    // weight chunk lo
#define OFF_PB  44032    // probs fp32 [64][129] (overlays dead weights)
#define OFF_H   84992    // h hi/lo bf16 [128][1040B] (hi 512B, lo 512B, pad 16B)
#define SMEM_TOTAL 218112

__device__ __forceinline__ uint32_t smem_u32(const void* p){
  uint32_t a; asm("{ .reg .u64 t; cvta.to.shared.u64 t, %1; cvt.u32.u64 %0, t; }":"=r"(a):"l"(p)); return a;
}
__device__ __forceinline__ void ldsm_x4(uint32_t* a, uint32_t addr){
  asm volatile("ldmatrix.sync.aligned.m8n8.x4.shared.b16 {%0,%1,%2,%3},[%4];"
    :"=r"(a[0]),"=r"(a[1]),"=r"(a[2]),"=r"(a[3]):"r"(addr));
}
__device__ __forceinline__ void ldsm_x2(uint32_t* b, uint32_t addr){
  asm volatile("ldmatrix.sync.aligned.m8n8.x2.shared.b16 {%0,%1},[%2];"
    :"=r"(b[0]),"=r"(b[1]):"r"(addr));
}
__device__ __forceinline__ void mma_bf16(float* d, const uint32_t* a, const uint32_t* b){
  asm volatile("mma.sync.aligned.m16n8k16.row.col.f32.bf16.bf16.f32 "
    "{%0,%1,%2,%3},{%4,%5,%6,%7},{%8,%9},{%0,%1,%2,%3};"
    :"+f"(d[0]),"+f"(d[1]),"+f"(d[2]),"+f"(d[3])
    :"r"(a[0]),"r"(a[1]),"r"(a[2]),"r"(a[3]),"r"(b[0]),"r"(b[1]));
}
__device__ __forceinline__ void split2(float x0,float x1,uint32_t&hi,uint32_t&lo){
  __nv_bfloat162 h=__floats2bfloat162_rn(x0,x1);
  float r0=x0-__bfloat162float(h.x), r1=x1-__bfloat162float(h.y);
  __nv_bfloat162 l2=__floats2bfloat162_rn(r0,r1);
  hi=*(uint32_t*)&h; lo=*(uint32_t*)&l2;
}

// Stage a weight chunk: src[row][c0 + 0..F4PR*4) fp32 -> hi/lo bf16 tiles (DSTRIDE bytes/row)
template<int ROWS,int F4PR,int DSTRIDE>
__device__ __forceinline__ void stage_w(char* sm,const float* __restrict__ src,int sstride,int c0,int tid){
  #pragma unroll
  for(int it=0; it<ROWS*F4PR/NT; ++it){
    int e=tid+it*NT;
    int row=e/F4PR, f4=e%F4PR;
    float4 v=*(const float4*)(src + row*sstride + c0 + f4*4);
    uint32_t hA,lA,hB,lB;
    split2(v.x,v.y,hA,lA); split2(v.z,v.w,hB,lB);
    *(uint2*)(sm+OFF_W  +row*DSTRIDE+f4*8)=make_uint2(hA,hB);
    *(uint2*)(sm+OFF_WLO+row*DSTRIDE+f4*8)=make_uint2(lA,lB);
  }
}

// One k16-tile sweep over NTILES n-tiles. aHi = A-frag ldmatrix base addr (lo at +512).
// kbyte = byte offset of this k16 tile inside the staged weight chunk row.
template<int NTILES,bool ALO,int WSTRIDE>
__device__ __forceinline__ void sweep(float (*acc)[4],uint32_t sb,uint32_t aHi,int kbyte,int ll){
  uint32_t ah[4],al[4];
  ldsm_x4(ah,aHi);
  if(ALO) ldsm_x4(al,aHi+512);
  #pragma unroll
  for(int nt=0;nt<NTILES;++nt){
    uint32_t bh[2],bl[2];
    uint32_t ba=sb+OFF_W+(uint32_t)((nt*8+(ll&7))*WSTRIDE)+kbyte+((ll>>3)<<4);
    ldsm_x2(bh,ba);
    mma_bf16(acc[nt],ah,bh);
    if(ALO) mma_bf16(acc[nt],al,bh);    // reuse Whi frag for Alo term
    ldsm_x2(bl,ba+(OFF_WLO-OFF_W));
    mma_bf16(acc[nt],ah,bl);
  }
}

// LayerNorm + ReLU on register fragments -> h hi/lo in smem (warp-private rows)
__device__ __forceinline__ void ln_store(char* sm,float (*acc)[4],int m0,int l,int pofs){
  const float* bb=(const float*)(sm+OFF_P)+pofs;
  const float* gg=bb+256; const float* be=bb+512;
  int g=l>>2,t=l&3,rA=m0+g,rB=rA+8;
  float sA=0,qA=0,sB=0,qB=0;
  #pragma unroll
  for(int nt=0;nt<32;++nt){
    int c0=8*nt+2*t;
    float b0=bb[c0],b1=bb[c0+1];
    acc[nt][0]+=b0; acc[nt][1]+=b1; acc[nt][2]+=b0; acc[nt][3]+=b1;
    sA+=acc[nt][0]+acc[nt][1]; qA+=acc[nt][0]*acc[nt][0]+acc[nt][1]*acc[nt][1];
    sB+=acc[nt][2]+acc[nt][3]; qB+=acc[nt][2]*acc[nt][2]+acc[nt][3]*acc[nt][3];
  }
  #pragma unroll
  for(int o=1;o<=2;o<<=1){
    sA+=__shfl_xor_sync(~0u,sA,o); qA+=__shfl_xor_sync(~0u,qA,o);
    sB+=__shfl_xor_sync(~0u,sB,o); qB+=__shfl_xor_sync(~0u,qB,o);
  }
  float muA=sA*(1.f/256.f), muB=sB*(1.f/256.f);
  float rsA=rsqrtf(fmaxf(qA*(1.f/256.f)-muA*muA,0.f)+1e-5f);
  float rsB=rsqrtf(fmaxf(qB*(1.f/256.f)-muB*muB,0.f)+1e-5f);
  #pragma unroll
  for(int nt=0;nt<32;++nt){
    int c0=8*nt+2*t;
    float h0=fmaxf(0.f,(acc[nt][0]-muA)*rsA*gg[c0]+be[c0]);
    float h1=fmaxf(0.f,(acc[nt][1]-muA)*rsA*gg[c0+1]+be[c0+1]);
    uint32_t hi,lo; split2(h0,h1,hi,lo);
    *(uint32_t*)(sm+OFF_H+rA*1040+c0*2)=hi;
    *(uint32_t*)(sm+OFF_H+rA*1040+512+c0*2)=lo;
    h0=fmaxf(0.f,(acc[nt][2]-muB)*rsB*gg[c0]+be[c0]);
    h1=fmaxf(0.f,(acc[nt][3]-muB)*rsB*gg[c0+1]+be[c0+1]);
    split2(h0,h1,hi,lo);
    *(uint32_t*)(sm+OFF_H+rB*1040+c0*2)=hi;
    *(uint32_t*)(sm+OFF_H+rB*1040+512+c0*2)=lo;
  }
}

extern "C" __global__ void __launch_bounds__(NT,1)
shiftdec_mma(const float* __restrict__ a_bits,const float* __restrict__ shift_bits,
  const float* __restrict__ W1,const float* __restrict__ b1,const float* __restrict__ g1,const float* __restrict__ be1,
  const float* __restrict__ W2,const float* __restrict__ b2,const float* __restrict__ g2,const float* __restrict__ be2,
  const float* __restrict__ W3,const float* __restrict__ b3,float* __restrict__ out)
{
  extern __shared__ char sm[];
  const uint32_t sb=smem_u32(sm);
  float* sPar=(float*)(sm+OFF_P);
  const int tid=threadIdx.x, w=tid>>5, l=tid&31, ll=l&15;
  const int m0=w*16, r0=blockIdx.x*128;

  sPar[tid]=b1[tid]; sPar[256+tid]=g1[tid]; sPar[512+tid]=be1[tid];
  sPar[768+tid]=b2[tid]; sPar[1024+tid]=g2[tid]; sPar[1280+tid]=be2[tid];
  if(tid<64) sPar[1536+tid]=b3[tid];

  { // stage X and a_bits as bf16 tiles (row stride 144B = 9 units, conflict-free)
    const float4* xs=(const float4*)(shift_bits+(size_t)r0*64);
    const float4* as=(const float4*)(a_bits+(size_t)r0*64);
    #pragma unroll
    for(int it=0;it<8;++it){
      int e=tid+it*NT, row=e>>4, f4=e&15;
      float4 v=xs[e];
      __nv_bfloat162 p0=__floats2bfloat162_rn(v.x,v.y),p1=__floats2bfloat162_rn(v.z,v.w);
      *(uint2*)(sm+OFF_X+row*144+f4*8)=make_uint2(*(uint32_t*)&p0,*(uint32_t*)&p1);
      v=as[e];
      p0=__floats2bfloat162_rn(v.x,v.y); p1=__floats2bfloat162_rn(v.z,v.w);
      *(uint2*)(sm+OFF_A+row*144+f4*8)=make_uint2(*(uint32_t*)&p0,*(uint32_t*)&p1);
    }
  }

  float acc[32][4];
  #pragma unroll
  for(int i=0;i<32;++i){acc[i][0]=acc[i][1]=acc[i][2]=acc[i][3]=0.f;}

  // ---- GEMM1: X[128x64] @ W1^T[64x256], 2 k-chunks of 32 (X exact -> 2 terms) ----
  #pragma unroll 1
  for(int c=0;c<2;++c){
    __syncthreads();
    stage_w<256,8,80>(sm,W1,64,c*32,tid);
    __syncthreads();
    #pragma unroll
    for(int kt=0;kt<2;++kt){
      uint32_t aaddr=sb+OFF_X+(uint32_t)((m0+ll)*144+(c*32+kt*16)*2)+(uint32_t)(l&16);
      sweep<32,false,80>(acc,sb,aaddr,kt*32,ll);
    }
  }
  __syncthreads();
  ln_store(sm,acc,m0,l,0);

  #pragma unroll
  for(int i=0;i<32;++i){acc[i][0]=acc[i][1]=acc[i][2]=acc[i][3]=0.f;}

  // ---- GEMM2: h1 @ W2^T[256x256], 8 k-chunks of 32, 3 terms ----
  #pragma unroll 1
  for(int c=0;c<8;++c){
    __syncthreads();
    stage_w<256,8,80>(sm,W2,256,c*32,tid);
    __syncthreads();
    #pragma unroll
    for(int kt=0;kt<2;++kt){
      uint32_t aaddr=sb+OFF_H+(uint32_t)((m0+ll)*1040+(c*32+kt*16)*2)+(uint32_t)(l&16);
      sweep<32,true,80>(acc,sb,aaddr,kt*32,ll);
    }
  }
  __syncthreads();
  ln_store(sm,acc,m0,l,768);

  #pragma unroll
  for(int i=0;i<8;++i){acc[i][0]=acc[i][1]=acc[i][2]=acc[i][3]=0.f;}

  // ---- GEMM3: h2 @ W3^T[256x64], 2 k-chunks of 128, 3 terms ----
  #pragma unroll 1
  for(int c=0;c<2;++c){
    __syncthreads();
    stage_w<64,32,272>(sm,W3,256,c*128,tid);
    __syncthreads();
    #pragma unroll
    for(int kt=0;kt<8;++kt){
      uint32_t aaddr=sb+OFF_H+(uint32_t)((m0+ll)*1040+(c*128+kt*16)*2)+(uint32_t)(l&16);
      sweep<8,true,272>(acc,sb,aaddr,kt*32,ll);
    }
  }
  __syncthreads();   // weights dead; probs region free

  // ---- softmax on acc[0..7] fragments; probs -> sPB[s][row] (stride 129 fp32) ----
  {
    int g=l>>2,t=l&3,rA=m0+g,rB=rA+8;
    float mA=-1e30f,mB=-1e30f;
    #pragma unroll
    for(int nt=0;nt<8;++nt){
      int c0=8*nt+2*t;
      acc[nt][0]+=sPar[1536+c0]; acc[nt][1]+=sPar[1537+c0];
      acc[nt][2]+=sPar[1536+c0]; acc[nt][3]+=sPar[1537+c0];
      mA=fmaxf(mA,fmaxf(acc[nt][0],acc[nt][1]));
      mB=fmaxf(mB,fmaxf(acc[nt][2],acc[nt][3]));
    }
    #pragma unroll
    for(int o=1;o<=2;o<<=1){ mA=fmaxf(mA,__shfl_xor_sync(~0u,mA,o)); mB=fmaxf(mB,__shfl_xor_sync(~0u,mB,o)); }
    float sA=0.f,sB=0.f;
    #pragma unroll
    for(int nt=0;nt<8;++nt){
      acc[nt][0]=__expf(acc[nt][0]-mA); acc[nt][1]=__expf(acc[nt][1]-mA);
      acc[nt][2]=__expf(acc[nt][2]-mB); acc[nt][3]=__expf(acc[nt][3]-mB);
      sA+=acc[nt][0]+acc[nt][1]; sB+=acc[nt][2]+acc[nt][3];
    }
    #pragma unroll
    for(int o=1;o<=2;o<<=1){ sA+=__shfl_xor_sync(~0u,sA,o); sB+=__shfl_xor_sync(~0u,sB,o); }
    float iA=1.f/sA, iB=1.f/sB;
    float* sP=(float*)(sm+OFF_PB);
    #pragma unroll
    for(int nt=0;nt<8;++nt){
      int c0=8*nt+2*t;
      sP[c0*129+rA]=acc[nt][0]*iA; sP[(c0+1)*129+rA]=acc[nt][1]*iA;
      sP[c0*129+rB]=acc[nt][2]*iB; sP[(c0+1)*129+rB]=acc[nt][3]*iB;
    }
  }
  __syncthreads();

  // ---- causal shift-sum: out[b,i] = sum_{s<=i} probs[b,s] * a[b,i-s] ----
  {
    const int q=w>>2, row=(w&3)*32+l;
    float areg[64];
    #pragma unroll
    for(int u=0;u<8;++u){
      uint4 v=*(const uint4*)(sm+OFF_A+row*144+u*16);
      __nv_bfloat162 q0=*(__nv_bfloat162*)&v.x,q1=*(__nv_bfloat162*)&v.y;
      __nv_bfloat162 q2=*(__nv_bfloat162*)&v.z,q3=*(__nv_bfloat162*)&v.w;
      areg[8*u+0]=__bfloat162float(q0.x); areg[8*u+1]=__bfloat162float(q0.y);
      areg[8*u+2]=__bfloat162float(q1.x); areg[8*u+3]=__bfloat162float(q1.y);
      areg[8*u+4]=__bfloat162float(q2.x); areg[8*u+5]=__bfloat162float(q2.y);
      areg[8*u+6]=__bfloat162float(q3.x); areg[8*u+7]=__bfloat162float(q3.y);
    }
    float o[32];
    #pragma unroll
    for(int j=0;j<32;++j)o[j]=0.f;
    const float* sP=(const float*)(sm+OFF_PB);
    if(q==0){
      #pragma unroll
      for(int s=0;s<32;++s){
        float pv=sP[s*129+row];
        #pragma unroll
        for(int j=0;j<32;++j) if(j>=s) o[j]+=pv*areg[j-s];
      }
    } else {
      #pragma unroll
      for(int s=0;s<64;++s){
        float pv=sP[s*129+row];
        #pragma unroll
        for(int j=0;j<32;++j) if(32+j-s>=0) o[j]+=pv*areg[32+j-s];
      }
    }
    float* op=out+(size_t)(r0+row)*64+q*32;
    #pragma unroll
    for(int c4=0;c4<8;++c4)
      *(float4*)(op+c4*4)=make_float4(o[4*c4],o[4*c4+1],o[4*c4+2],o[4*c4+3]);
  }
}

extern "C" void kernel_launch(void* const* d_in, const int* in_sizes, int n_in,
                              void* d_out, int out_size)
{
  const float* a_bits     = (const float*)d_in[0];
  const float* shift_bits = (const float*)d_in[1];
  const float* W1  = (const float*)d_in[2];
  const float* b1  = (const float*)d_in[3];
  const float* g1  = (const float*)d_in[4];
  const float* be1 = (const float*)d_in[5];
  const float* W2  = (const float*)d_in[6];
  const float* b2  = (const float*)d_in[7];
  const float* g2  = (const float*)d_in[8];
  const float* be2 = (const float*)d_in[9];
  const float* W3  = (const float*)d_in[10];
  const float* b3  = (const float*)d_in[11];
  float* out = (float*)d_out;

  const int B = in_sizes[0] / 64;      // 32768
  const int grid = B / 128;            // 256

  cudaFuncSetAttribute(shiftdec_mma,
                       cudaFuncAttributeMaxDynamicSharedMemorySize, SMEM_TOTAL);
  shiftdec_mma<<<grid, NT, SMEM_TOTAL>>>(a_bits, shift_bits,
                                         W1, b1, g1, be1,
                                         W2, b2, g2, be2,
                                         W3, b3, out);
}

// round 9
// speedup vs baseline: 3.2514x; 1.5254x over previous
#include <cuda_runtime.h>
#include <cuda_bf16.h>
#include <cstdint>

// ShiftDecoderNet via mma.sync m16n8k16 bf16 + prepass weight conversion +
// cp.async double-buffered weight staging. CTA = 128 rows, grid = 256.

#define NT 256
#define OFF_P   0        // params: 1600 floats
#define OFF_X   6656     // X bf16 [128][144B]
#define OFF_A   25088    // a_bits bf16 [128][144B]
#define OFF_WB  43520    // 2 weight buffers x 24576B (hi plane + lo plane)
#define OFF_PB  43520    // probs fp32 [64][129] overlays weight buffers
#define OFF_H   92672    // h hi/lo bf16 [128][1040B]
#define SMEM_TOTAL 225792
#define WBUF 24576

// preconverted weights: [chunk][hi plane][lo plane], rows padded to 48B
__device__ __align__(16) unsigned char gW1d[4  * 24576];  // 256 rows, lo at +12288
__device__ __align__(16) unsigned char gW2d[16 * 24576];  // 256 rows, lo at +12288
__device__ __align__(16) unsigned char gW3d[16 * 6144];   // 64 rows,  lo at +3072

__device__ __forceinline__ uint32_t smem_u32(const void* p){
  uint32_t a; asm("{ .reg .u64 t; cvta.to.shared.u64 t, %1; cvt.u32.u64 %0, t; }":"=r"(a):"l"(p)); return a;
}
__device__ __forceinline__ void ldsm_x4(uint32_t* a, uint32_t addr){
  asm volatile("ldmatrix.sync.aligned.m8n8.x4.shared.b16 {%0,%1,%2,%3},[%4];"
    :"=r"(a[0]),"=r"(a[1]),"=r"(a[2]),"=r"(a[3]):"r"(addr));
}
__device__ __forceinline__ void ldsm_x2(uint32_t* b, uint32_t addr){
  asm volatile("ldmatrix.sync.aligned.m8n8.x2.shared.b16 {%0,%1},[%2];"
    :"=r"(b[0]),"=r"(b[1]):"r"(addr));
}
__device__ __forceinline__ void mma_bf16(float* d, const uint32_t* a, const uint32_t* b){
  asm volatile("mma.sync.aligned.m16n8k16.row.col.f32.bf16.bf16.f32 "
    "{%0,%1,%2,%3},{%4,%5,%6,%7},{%8,%9},{%0,%1,%2,%3};"
    :"+f"(d[0]),"+f"(d[1]),"+f"(d[2]),"+f"(d[3])
    :"r"(a[0]),"r"(a[1]),"r"(a[2]),"r"(a[3]),"r"(b[0]),"r"(b[1]));
}
__device__ __forceinline__ void split2(float x0,float x1,uint32_t&hi,uint32_t&lo){
  __nv_bfloat162 h=__floats2bfloat162_rn(x0,x1);
  float r0=x0-__bfloat162float(h.x), r1=x1-__bfloat162float(h.y);
  __nv_bfloat162 l2=__floats2bfloat162_rn(r0,r1);
  hi=*(uint32_t*)&h; lo=*(uint32_t*)&l2;
}
#define CP16(dst,src) asm volatile("cp.async.cg.shared.global [%0],[%1],16;"::"r"(dst),"l"(src))
#define CPCOMMIT() asm volatile("cp.async.commit_group;" ::: "memory")
#define CPWAIT1() asm volatile("cp.async.wait_group 1;" ::: "memory")
#define CPWAIT0() asm volatile("cp.async.wait_group 0;" ::: "memory")

// ---------- prepass: fp32 weights -> bf16 hi/lo tile planes in global ----------
extern "C" __global__ void __launch_bounds__(NT,1)
prep_weights(const float* __restrict__ W1,const float* __restrict__ W2,const float* __restrict__ W3){
  int t = blockIdx.x*NT + threadIdx.x;     // one bf16x2 pair (2 k-values) per thread
  if(t < 8192){                            // W1: 256n x 64k
    int n=t>>5, k=(t&31)*2, kk=k&15;
    uint32_t hi,lo; split2(W1[n*64+k],W1[n*64+k+1],hi,lo);
    int off=(k>>4)*24576 + n*48 + (kk>>3)*16 + (kk&7)*2;
    *(uint32_t*)(gW1d+off)=hi; *(uint32_t*)(gW1d+off+12288)=lo;
  } else if(t < 40960){                    // W2: 256n x 256k
    int t2=t-8192, n=t2>>7, k=(t2&127)*2, kk=k&15;
    uint32_t hi,lo; split2(W2[n*256+k],W2[n*256+k+1],hi,lo);
    int off=(k>>4)*24576 + n*48 + (kk>>3)*16 + (kk&7)*2;
    *(uint32_t*)(gW2d+off)=hi; *(uint32_t*)(gW2d+off+12288)=lo;
  } else if(t < 49152){                    // W3: 64n x 256k
    int t3=t-40960, n=t3>>7, k=(t3&127)*2, kk=k&15;
    uint32_t hi,lo; split2(W3[n*256+k],W3[n*256+k+1],hi,lo);
    int off=(k>>4)*6144 + n*48 + (kk>>3)*16 + (kk&7)*2;
    *(uint32_t*)(gW3d+off)=hi; *(uint32_t*)(gW3d+off+3072)=lo;
  }
}

// prefetch one chunk (CHB bytes) into buffer `buf`
template<int CHB>
__device__ __forceinline__ void pf(uint32_t wb,int buf,const unsigned char* g,int c,int tid){
  const unsigned char* src = g + (size_t)c*CHB;
  uint32_t dst = wb + buf*WBUF;
  constexpr int TOT = CHB/16;
  #pragma unroll
  for(int i=0;i<(TOT+NT-1)/NT;++i){
    int e=tid+i*NT;
    if(TOT%NT==0 || e<TOT) CP16(dst+e*16, src+(size_t)e*16);
  }
  CPCOMMIT();
}

// one k16 chunk sweep: NTILES n-tiles, 3-term (or 2-term) split-bf16 mma
template<int NTILES,bool ALO>
__device__ __forceinline__ void sweep16(float (*acc)[4],uint32_t wbase,uint32_t loofs,uint32_t aHi,int ll){
  uint32_t ah[4],al[4];
  ldsm_x4(ah,aHi);
  if(ALO) ldsm_x4(al,aHi+512);
  #pragma unroll
  for(int nt=0;nt<NTILES;++nt){
    uint32_t bh[2],bl[2];
    uint32_t ba = wbase + (uint32_t)((nt*8+(ll&7))*48 + ((ll>>3)&1)*16);
    ldsm_x2(bh,ba);
    mma_bf16(acc[nt],ah,bh);
    if(ALO) mma_bf16(acc[nt],al,bh);
    ldsm_x2(bl,ba+loofs);
    mma_bf16(acc[nt],ah,bl);
  }
}

// LayerNorm + ReLU on fragments -> h hi/lo smem (warp-private rows)
__device__ __forceinline__ void ln_store(char* sm,float (*acc)[4],int m0,int l,int pofs){
  const float* bb=(const float*)(sm+OFF_P)+pofs;
  const float* gg=bb+256; const float* be=bb+512;
  int g=l>>2,t=l&3,rA=m0+g,rB=rA+8;
  float sA=0,qA=0,sB=0,qB=0;
  #pragma unroll
  for(int nt=0;nt<32;++nt){
    int c0=8*nt+2*t;
    float b0=bb[c0],b1=bb[c0+1];
    acc[nt][0]+=b0; acc[nt][1]+=b1; acc[nt][2]+=b0; acc[nt][3]+=b1;
    sA+=acc[nt][0]+acc[nt][1]; qA+=acc[nt][0]*acc[nt][0]+acc[nt][1]*acc[nt][1];
    sB+=acc[nt][2]+acc[nt][3]; qB+=acc[nt][2]*acc[nt][2]+acc[nt][3]*acc[nt][3];
  }
  #pragma unroll
  for(int o=1;o<=2;o<<=1){
    sA+=__shfl_xor_sync(~0u,sA,o); qA+=__shfl_xor_sync(~0u,qA,o);
    sB+=__shfl_xor_sync(~0u,sB,o); qB+=__shfl_xor_sync(~0u,qB,o);
  }
  float muA=sA*(1.f/256.f), muB=sB*(1.f/256.f);
  float rsA=rsqrtf(fmaxf(qA*(1.f/256.f)-muA*muA,0.f)+1e-5f);
  float rsB=rsqrtf(fmaxf(qB*(1.f/256.f)-muB*muB,0.f)+1e-5f);
  #pragma unroll
  for(int nt=0;nt<32;++nt){
    int c0=8*nt+2*t;
    float h0=fmaxf(0.f,(acc[nt][0]-muA)*rsA*gg[c0]+be[c0]);
    float h1=fmaxf(0.f,(acc[nt][1]-muA)*rsA*gg[c0+1]+be[c0+1]);
    uint32_t hi,lo; split2(h0,h1,hi,lo);
    *(uint32_t*)(sm+OFF_H+rA*1040+c0*2)=hi;
    *(uint32_t*)(sm+OFF_H+rA*1040+512+c0*2)=lo;
    h0=fmaxf(0.f,(acc[nt][2]-muB)*rsB*gg[c0]+be[c0]);
    h1=fmaxf(0.f,(acc[nt][3]-muB)*rsB*gg[c0+1]+be[c0+1]);
    split2(h0,h1,hi,lo);
    *(uint32_t*)(sm+OFF_H+rB*1040+c0*2)=hi;
    *(uint32_t*)(sm+OFF_H+rB*1040+512+c0*2)=lo;
  }
}

extern "C" __global__ void __launch_bounds__(NT,1)
shiftdec_mma(const float* __restrict__ a_bits,const float* __restrict__ shift_bits,
  const float* __restrict__ b1,const float* __restrict__ g1,const float* __restrict__ be1,
  const float* __restrict__ b2,const float* __restrict__ g2,const float* __restrict__ be2,
  const float* __restrict__ b3,float* __restrict__ out)
{
  extern __shared__ char sm[];
  const uint32_t sb=smem_u32(sm);
  const uint32_t wb=sb+OFF_WB;
  float* sPar=(float*)(sm+OFF_P);
  const int tid=threadIdx.x, w=tid>>5, l=tid&31, ll=l&15;
  const int m0=w*16, r0=blockIdx.x*128;

  // kick off GEMM1 weight prefetches immediately
  pf<24576>(wb,0,gW1d,0,tid);
  pf<24576>(wb,1,gW1d,1,tid);

  sPar[tid]=b1[tid]; sPar[256+tid]=g1[tid]; sPar[512+tid]=be1[tid];
  sPar[768+tid]=b2[tid]; sPar[1024+tid]=g2[tid]; sPar[1280+tid]=be2[tid];
  if(tid<64) sPar[1536+tid]=b3[tid];

  { // stage X and a_bits as bf16 tiles (144B rows)
    const float4* xs=(const float4*)(shift_bits+(size_t)r0*64);
    const float4* as=(const float4*)(a_bits+(size_t)r0*64);
    #pragma unroll
    for(int it=0;it<8;++it){
      int e=tid+it*NT, row=e>>4, f4=e&15;
      float4 v=xs[e];
      __nv_bfloat162 p0=__floats2bfloat162_rn(v.x,v.y),p1=__floats2bfloat162_rn(v.z,v.w);
      *(uint2*)(sm+OFF_X+row*144+f4*8)=make_uint2(*(uint32_t*)&p0,*(uint32_t*)&p1);
      v=as[e];
      p0=__floats2bfloat162_rn(v.x,v.y); p1=__floats2bfloat162_rn(v.z,v.w);
      *(uint2*)(sm+OFF_A+row*144+f4*8)=make_uint2(*(uint32_t*)&p0,*(uint32_t*)&p1);
    }
  }

  float acc[32][4];
  #pragma unroll
  for(int i=0;i<32;++i){acc[i][0]=acc[i][1]=acc[i][2]=acc[i][3]=0.f;}

  // ---- GEMM1: X @ W1^T, 4 k16 chunks, 2 terms (X exact in bf16) ----
  #pragma unroll 1
  for(int c=0;c<4;++c){
    if(c<3) CPWAIT1(); else CPWAIT0();
    __syncthreads();
    uint32_t aaddr=sb+OFF_X+(uint32_t)((m0+ll)*144+c*32)+(uint32_t)(l&16);
    sweep16<32,false>(acc,wb+(c&1)*WBUF,12288,aaddr,ll);
    __syncthreads();
    if(c+2<4) pf<24576>(wb,c&1,gW1d,c+2,tid);
  }
  // prologue for GEMM2 overlaps LN1
  pf<24576>(wb,0,gW2d,0,tid);
  pf<24576>(wb,1,gW2d,1,tid);
  ln_store(sm,acc,m0,l,0);

  #pragma unroll
  for(int i=0;i<32;++i){acc[i][0]=acc[i][1]=acc[i][2]=acc[i][3]=0.f;}

  // ---- GEMM2: h1 @ W2^T, 16 k16 chunks, 3 terms ----
  #pragma unroll 1
  for(int c=0;c<16;++c){
    if(c<15) CPWAIT1(); else CPWAIT0();
    __syncthreads();
    uint32_t aaddr=sb+OFF_H+(uint32_t)((m0+ll)*1040+c*32)+(uint32_t)(l&16);
    sweep16<32,true>(acc,wb+(c&1)*WBUF,12288,aaddr,ll);
    __syncthreads();
    if(c+2<16) pf<24576>(wb,c&1,gW2d,c+2,tid);
  }
  // prologue for GEMM3 overlaps LN2
  pf<6144>(wb,0,gW3d,0,tid);
  pf<6144>(wb,1,gW3d,1,tid);
  ln_store(sm,acc,m0,l,768);

  #pragma unroll
  for(int i=0;i<8;++i){acc[i][0]=acc[i][1]=acc[i][2]=acc[i][3]=0.f;}

  // ---- GEMM3: h2 @ W3^T, 16 k16 chunks, 3 terms, N=64 ----
  #pragma unroll 1
  for(int c=0;c<16;++c){
    if(c<15) CPWAIT1(); else CPWAIT0();
    __syncthreads();
    uint32_t aaddr=sb+OFF_H+(uint32_t)((m0+ll)*1040+c*32)+(uint32_t)(l&16);
    sweep16<8,true>(acc,wb+(c&1)*WBUF,3072,aaddr,ll);
    __syncthreads();
    if(c+2<16) pf<6144>(wb,c&1,gW3d,c+2,tid);
  }

  // ---- softmax on acc[0..7]; probs -> sP[s][row] (stride 129 fp32) ----
  {
    int g=l>>2,t=l&3,rA=m0+g,rB=rA+8;
    float mA=-1e30f,mB=-1e30f;
    #pragma unroll
    for(int nt=0;nt<8;++nt){
      int c0=8*nt+2*t;
      acc[nt][0]+=sPar[1536+c0]; acc[nt][1]+=sPar[1537+c0];
      acc[nt][2]+=sPar[1536+c0]; acc[nt][3]+=sPar[1537+c0];
      mA=fmaxf(mA,fmaxf(acc[nt][0],acc[nt][1]));
      mB=fmaxf(mB,fmaxf(acc[nt][2],acc[nt][3]));
    }
    #pragma unroll
    for(int o=1;o<=2;o<<=1){ mA=fmaxf(mA,__shfl_xor_sync(~0u,mA,o)); mB=fmaxf(mB,__shfl_xor_sync(~0u,mB,o)); }
    float sA=0.f,sB=0.f;
    #pragma unroll
    for(int nt=0;nt<8;++nt){
      acc[nt][0]=__expf(acc[nt][0]-mA); acc[nt][1]=__expf(acc[nt][1]-mA);
      acc[nt][2]=__expf(acc[nt][2]-mB); acc[nt][3]=__expf(acc[nt][3]-mB);
      sA+=acc[nt][0]+acc[nt][1]; sB+=acc[nt][2]+acc[nt][3];
    }
    #pragma unroll
    for(int o=1;o<=2;o<<=1){ sA+=__shfl_xor_sync(~0u,sA,o); sB+=__shfl_xor_sync(~0u,sB,o); }
    float iA=1.f/sA, iB=1.f/sB;
    float* sP=(float*)(sm+OFF_PB);
    #pragma unroll
    for(int nt=0;nt<8;++nt){
      int c0=8*nt+2*t;
      sP[c0*129+rA]=acc[nt][0]*iA; sP[(c0+1)*129+rA]=acc[nt][1]*iA;
      sP[c0*129+rB]=acc[nt][2]*iB; sP[(c0+1)*129+rB]=acc[nt][3]*iB;
    }
  }
  __syncthreads();

  // ---- causal shift-sum ----
  {
    const int q=w>>2, row=(w&3)*32+l;
    float areg[64];
    #pragma unroll
    for(int u=0;u<8;++u){
      uint4 v=*(const uint4*)(sm+OFF_A+row*144+u*16);
      __nv_bfloat162 q0=*(__nv_bfloat162*)&v.x,q1=*(__nv_bfloat162*)&v.y;
      __nv_bfloat162 q2=*(__nv_bfloat162*)&v.z,q3=*(__nv_bfloat162*)&v.w;
      areg[8*u+0]=__bfloat162float(q0.x); areg[8*u+1]=__bfloat162float(q0.y);
      areg[8*u+2]=__bfloat162float(q1.x); areg[8*u+3]=__bfloat162float(q1.y);
      areg[8*u+4]=__bfloat162float(q2.x); areg[8*u+5]=__bfloat162float(q2.y);
      areg[8*u+6]=__bfloat162float(q3.x); areg[8*u+7]=__bfloat162float(q3.y);
    }
    float o[32];
    #pragma unroll
    for(int j=0;j<32;++j)o[j]=0.f;
    const float* sP=(const float*)(sm+OFF_PB);
    if(q==0){
      #pragma unroll
      for(int s=0;s<32;++s){
        float pv=sP[s*129+row];
        #pragma unroll
        for(int j=0;j<32;++j) if(j>=s) o[j]+=pv*areg[j-s];
      }
    } else {
      #pragma unroll
      for(int s=0;s<64;++s){
        float pv=sP[s*129+row];
        #pragma unroll
        for(int j=0;j<32;++j) if(32+j-s>=0) o[j]+=pv*areg[32+j-s];
      }
    }
    float* op=out+(size_t)(r0+row)*64+q*32;
    #pragma unroll
    for(int c4=0;c4<8;++c4)
      *(float4*)(op+c4*4)=make_float4(o[4*c4],o[4*c4+1],o[4*c4+2],o[4*c4+3]);
  }
}

extern "C" void kernel_launch(void* const* d_in, const int* in_sizes, int n_in,
                              void* d_out, int out_size)
{
  const float* a_bits     = (const float*)d_in[0];
  const float* shift_bits = (const float*)d_in[1];
  const float* W1  = (const float*)d_in[2];
  const float* b1  = (const float*)d_in[3];
  const float* g1  = (const float*)d_in[4];
  const float* be1 = (const float*)d_in[5];
  const float* W2  = (const float*)d_in[6];
  const float* b2  = (const float*)d_in[7];
  const float* g2  = (const float*)d_in[8];
  const float* be2 = (const float*)d_in[9];
  const float* W3  = (const float*)d_in[10];
  const float* b3  = (const float*)d_in[11];
  float* out = (float*)d_out;

  const int B = in_sizes[0] / 64;      // 32768
  const int grid = B / 128;            // 256

  prep_weights<<<192, NT>>>(W1, W2, W3);

  cudaFuncSetAttribute(shiftdec_mma,
                       cudaFuncAttributeMaxDynamicSharedMemorySize, SMEM_TOTAL);
  shiftdec_mma<<<grid, NT, SMEM_TOTAL>>>(a_bits, shift_bits,
                                         b1, g1, be1,
                                         b2, g2, be2,
                                         b3, out);
}